// round 11
// baseline (speedup 1.0000x reference)
#include <cuda_runtime.h>
#include <cuda_bf16.h>
#include <cstdint>

#define BEV_H 512
#define BEV_W 512
#define BEV_C 64
#define HW (BEV_H * BEV_W)     // 262144 = 2^18
#define TILE 512               // cells per CTA
#define ROWP 516               // padded row length in words (2064B, 16B-mult)

// Scratch: last-writer pillar index per BEV cell (up to 8 batches).
__device__ int g_last[8 * HW];
// Zero row for empty cells (zero-initialized, never written).
__device__ __align__(16) float g_zero[BEV_C];

// ---------------------------------------------------------------------------
// Scatter: last-occurrence-wins via atomicMax on pillar index.
// ---------------------------------------------------------------------------
__global__ void bev_scatter_kernel(const int* __restrict__ coords, int P) {
    int t = blockIdx.x * blockDim.x + threadIdx.x;
    int p0 = t * 4;
    if (p0 + 3 < P) {
        const int4* c4 = reinterpret_cast<const int4*>(coords + p0 * 3);
        int4 a  = __ldg(c4 + 0);  // b0 r0 c0 b1
        int4 bb = __ldg(c4 + 1);  // r1 c1 b2 r2
        int4 cc = __ldg(c4 + 2);  // c2 b3 r3 c3
        int bs[4] = {a.x, a.w, bb.z, cc.y};
        int rs[4] = {a.y, bb.x, bb.w, cc.z};
        int cs[4] = {a.z, bb.y, cc.x, cc.w};
#pragma unroll
        for (int k = 0; k < 4; k++) {
            int r = min(max(rs[k], 0), BEV_H - 1);
            int c = min(max(cs[k], 0), BEV_W - 1);
            atomicMax(&g_last[bs[k] * HW + r * BEV_W + c], p0 + k);
        }
    } else if (p0 < P) {
        for (int p = p0; p < P; p++) {
            int b = coords[3 * p + 0];
            int r = min(max(coords[3 * p + 1], 0), BEV_H - 1);
            int c = min(max(coords[3 * p + 2], 0), BEV_W - 1);
            atomicMax(&g_last[b * HW + r * BEV_W + c], p);
        }
    }
}

// ---------------------------------------------------------------------------
// Gather + transpose with TMA bulk stores (SM never issues an output STG).
// CTA = 512 threads, tile = 512 consecutive cells.
//   smem: 64 channel rows x 516 words (padded): row ch holds out[b][ch][pos..
//   pos+512) contiguously; pad word 516 makes STS banks (4ch+cell)%32 ->
//   at most 2-way conflicts for the team store pattern.
//   Load: 4-lane team per cell (lane q loads float4 chunks q,q+4,q+8,q+12);
//   thread covers 4 cells (team, +128, +256, +384); all 16 LDG.128 issued
//   up front (1 CTA/SM -> registers are free).
//   Store: barrier -> fence.proxy.async -> threads 0..63 each issue ONE
//   cp.async.bulk of their 2KB channel row -> TMA engine writes global.
//   wait_group.read 0 (source-read-done only) before CTA exit.
// ---------------------------------------------------------------------------
__global__ void __launch_bounds__(512, 1) bev_gather_kernel(
    const float* __restrict__ feats,
    float* __restrict__ out) {
    extern __shared__ float sbuf[];              // 64 * 516 floats = 132KB

    const int tid  = threadIdx.x;
    const int q    = tid & 3;                    // lane within 4-lane team
    const int team = tid >> 2;                   // 0..127

    const int base = blockIdx.x * TILE;          // tile never crosses a batch
    const int b    = base >> 18;
    const int pos  = base & (HW - 1);

    // ---- load g_last for this thread's 4 cells (8 addrs/warp -> 1 wf) ----
    int lc[4];
#pragma unroll
    for (int s = 0; s < 4; s++)
        lc[s] = __ldg(&g_last[base + team + 128 * s]);

    // ---- issue all 16 LDG.128 (max MLP; regs are free at 1 CTA/SM) ----
    float4 V[4][4];
#pragma unroll
    for (int s = 0; s < 4; s++) {
        const float4* row = reinterpret_cast<const float4*>(
            lc[s] >= 0 ? feats + (size_t)lc[s] * BEV_C : g_zero);
#pragma unroll
        for (int k = 0; k < 4; k++)
            V[s][k] = __ldg(row + q + 4 * k);
    }

    // ---- STS into channel-major padded rows ----
#pragma unroll
    for (int s = 0; s < 4; s++) {
        const int cell = team + 128 * s;
#pragma unroll
        for (int k = 0; k < 4; k++) {
            const int chb = 4 * (q + 4 * k);     // channel base 4q+16k
            float* p = sbuf + chb * ROWP + cell;
            p[0 * ROWP] = V[s][k].x;
            p[1 * ROWP] = V[s][k].y;
            p[2 * ROWP] = V[s][k].z;
            p[3 * ROWP] = V[s][k].w;
        }
    }

    __syncthreads();

    // ---- TMA bulk stores: one 2KB channel row per thread (tid < 64) ----
    if (tid < BEV_C) {
        asm volatile("fence.proxy.async.shared::cta;" ::: "memory");
        unsigned src;
        asm volatile("{ .reg .u64 t; cvta.to.shared.u64 t, %1; cvt.u32.u64 %0, t; }"
                     : "=r"(src) : "l"(sbuf + tid * ROWP));
        float* dst = out + (size_t)b * (BEV_C * HW) + (size_t)tid * HW + pos;
        asm volatile(
            "cp.async.bulk.global.shared::cta.bulk_group [%0], [%1], %2;"
            :: "l"(dst), "r"(src), "r"(TILE * 4) : "memory");
        asm volatile("cp.async.bulk.commit_group;" ::: "memory");
        // Wait only until TMA has READ the smem (not full write completion):
        // smem must not be deallocated/reused while reads are pending.
        asm volatile("cp.async.bulk.wait_group.read 0;" ::: "memory");
    }
}

extern "C" void kernel_launch(void* const* d_in, const int* in_sizes, int n_in,
                              void* d_out, int out_size) {
    const float* feats  = (const float*)d_in[0];   // (P, 64) float32
    const int*   coords = (const int*)d_in[1];     // (P, 3) int32
    float*       out    = (float*)d_out;           // (B, 64, 512, 512) float32

    int P = in_sizes[0] / BEV_C;
    int B = out_size / (BEV_C * HW);
    if (B > 8) B = 8;
    int ncells = B * HW;

    // 1) init last-index grid to -1 (memset node; 0xFF bytes == -1 int)
    void* lastPtr = nullptr;
    cudaGetSymbolAddress(&lastPtr, g_last);
    cudaMemsetAsync(lastPtr, 0xFF, (size_t)ncells * sizeof(int), 0);

    // 2) scatter
    int nt = (P + 3) / 4;
    bev_scatter_kernel<<<(nt + 255) / 256, 256>>>(coords, P);

    // 3) gather + transpose + TMA store: 512 cells per CTA, 132KB smem
    static bool attr_set = false;
    if (!attr_set) {
        cudaFuncSetAttribute(bev_gather_kernel,
                             cudaFuncAttributeMaxDynamicSharedMemorySize,
                             BEV_C * ROWP * 4);
        attr_set = true;
    }
    bev_gather_kernel<<<ncells / TILE, 512, BEV_C * ROWP * 4>>>(feats, out);
}

// round 12
// speedup vs baseline: 1.1185x; 1.1185x over previous
#include <cuda_runtime.h>
#include <cuda_bf16.h>
#include <cstdint>

#define BEV_H 512
#define BEV_W 512
#define BEV_C 64
#define HW (BEV_H * BEV_W)     // 262144 = 2^18
#define TILE 128               // cells per pipeline stage
#define ROWP 132               // padded row words (528B, 16B multiple)
#define STAGE (BEV_C * ROWP)   // words per stage (33792B)
#define GT 256                 // gather threads per CTA

// Scratch: last-writer pillar index per BEV cell (up to 8 batches).
__device__ int g_last[8 * HW];
// Zero row for empty cells (zero-initialized, never written).
__device__ __align__(16) float g_zero[BEV_C];

// ---------------------------------------------------------------------------
// Scatter: last-occurrence-wins via atomicMax on pillar index.
// ---------------------------------------------------------------------------
__global__ void bev_scatter_kernel(const int* __restrict__ coords, int P) {
    int t = blockIdx.x * blockDim.x + threadIdx.x;
    int p0 = t * 4;
    if (p0 + 3 < P) {
        const int4* c4 = reinterpret_cast<const int4*>(coords + p0 * 3);
        int4 a  = __ldg(c4 + 0);  // b0 r0 c0 b1
        int4 bb = __ldg(c4 + 1);  // r1 c1 b2 r2
        int4 cc = __ldg(c4 + 2);  // c2 b3 r3 c3
        int bs[4] = {a.x, a.w, bb.z, cc.y};
        int rs[4] = {a.y, bb.x, bb.w, cc.z};
        int cs[4] = {a.z, bb.y, cc.x, cc.w};
#pragma unroll
        for (int k = 0; k < 4; k++) {
            int r = min(max(rs[k], 0), BEV_H - 1);
            int c = min(max(cs[k], 0), BEV_W - 1);
            atomicMax(&g_last[bs[k] * HW + r * BEV_W + c], p0 + k);
        }
    } else if (p0 < P) {
        for (int p = p0; p < P; p++) {
            int b = coords[3 * p + 0];
            int r = min(max(coords[3 * p + 1], 0), BEV_H - 1);
            int c = min(max(coords[3 * p + 2], 0), BEV_W - 1);
            atomicMax(&g_last[b * HW + r * BEV_W + c], p);
        }
    }
}

// ---------------------------------------------------------------------------
// Persistent pipelined gather + transpose with TMA bulk stores.
// 256 threads/CTA, TILE=128 cells/stage, double-buffered smem (2 x 33KB ->
// 3 CTAs/SM). Grid-stride over tiles. Steady state per iteration:
//   STS tile t -> bar -> (tid<64) fence + cp.async.bulk row stores + commit
//   -> ALL threads issue next tile's 8 LDG.128 (fly under TMA drain)
//   -> (tid<64) wait_group.read 1 (other buffer read-complete) -> bar -> flip.
// Loads: 4-lane team per cell (lane q loads chunks q,q+4,q+8,q+12); thread
//   covers cells team, team+64. smem row ch holds the tile's 128 cell values
//   contiguously (TMA-readable); pad to 132 words -> STS 2-way worst case.
// SM never issues an output STG; TMA writes 64 x 512B per tile.
// ---------------------------------------------------------------------------
__global__ void __launch_bounds__(GT) bev_gather_kernel(
    const float* __restrict__ feats,
    float* __restrict__ out,
    int ntiles) {
    extern __shared__ float sbuf[];              // 2 * STAGE floats

    const int tid  = threadIdx.x;
    const int q    = tid & 3;                    // lane within 4-lane team
    const int team = tid >> 2;                   // 0..63

    const int stride = gridDim.x;
    int t = blockIdx.x;
    if (t >= ntiles) return;

    // ---- prologue: load tile t ----
    float4 V[2][4];
    {
        const int base = t * TILE;
#pragma unroll
        for (int s = 0; s < 2; s++) {
            const int lc = __ldg(&g_last[base + team + 64 * s]);
            const float4* row = reinterpret_cast<const float4*>(
                lc >= 0 ? feats + (size_t)lc * BEV_C : g_zero);
#pragma unroll
            for (int k = 0; k < 4; k++)
                V[s][k] = __ldg(row + q + 4 * k);
        }
    }

    int p = 0;
    while (true) {
        // ---- STS tile t into buf p (channel-major padded rows) ----
        float* buf = sbuf + p * STAGE;
#pragma unroll
        for (int s = 0; s < 2; s++) {
            const int cell = team + 64 * s;
#pragma unroll
            for (int k = 0; k < 4; k++) {
                const int chb = 4 * (q + 4 * k);       // channels chb..chb+3
                float* ptr = buf + chb * ROWP + cell;
                ptr[0 * ROWP] = V[s][k].x;
                ptr[1 * ROWP] = V[s][k].y;
                ptr[2 * ROWP] = V[s][k].z;
                ptr[3 * ROWP] = V[s][k].w;
            }
        }
        __syncthreads();

        // ---- TMA bulk stores for tile t (one 512B row per thread<64) ----
        if (tid < BEV_C) {
            asm volatile("fence.proxy.async.shared::cta;" ::: "memory");
            unsigned src;
            asm volatile(
                "{ .reg .u64 tt; cvta.to.shared.u64 tt, %1; cvt.u32.u64 %0, tt; }"
                : "=r"(src) : "l"(buf + tid * ROWP));
            const int b   = t >> 11;                   // tile/(HW/TILE=2048)
            const int pos = (t & 2047) * TILE;
            float* dst = out + (size_t)b * (BEV_C * HW) + (size_t)tid * HW + pos;
            asm volatile(
                "cp.async.bulk.global.shared::cta.bulk_group [%0], [%1], %2;"
                :: "l"(dst), "r"(src), "r"(TILE * 4) : "memory");
            asm volatile("cp.async.bulk.commit_group;" ::: "memory");
        }

        // ---- issue next tile's loads while TMA drains buf p ----
        const int tn = t + stride;
        const bool have_next = tn < ntiles;
        if (have_next) {
            const int base = tn * TILE;
#pragma unroll
            for (int s = 0; s < 2; s++) {
                const int lc = __ldg(&g_last[base + team + 64 * s]);
                const float4* row = reinterpret_cast<const float4*>(
                    lc >= 0 ? feats + (size_t)lc * BEV_C : g_zero);
#pragma unroll
                for (int k = 0; k < 4; k++)
                    V[s][k] = __ldg(row + q + 4 * k);
            }
        }

        if (!have_next) break;

        // ---- gate reuse of the other buffer: its group must be read-done ----
        if (tid < BEV_C)
            asm volatile("cp.async.bulk.wait_group.read 1;" ::: "memory");
        __syncthreads();

        t = tn;
        p ^= 1;
    }

    // ---- epilogue: all bulk writes must complete before exit ----
    if (tid < BEV_C)
        asm volatile("cp.async.bulk.wait_group 0;" ::: "memory");
}

extern "C" void kernel_launch(void* const* d_in, const int* in_sizes, int n_in,
                              void* d_out, int out_size) {
    const float* feats  = (const float*)d_in[0];   // (P, 64) float32
    const int*   coords = (const int*)d_in[1];     // (P, 3) int32
    float*       out    = (float*)d_out;           // (B, 64, 512, 512) float32

    int P = in_sizes[0] / BEV_C;
    int B = out_size / (BEV_C * HW);
    if (B > 8) B = 8;
    int ncells = B * HW;
    int ntiles = ncells / TILE;

    // 1) init last-index grid to -1 (memset node; 0xFF bytes == -1 int)
    void* lastPtr = nullptr;
    cudaGetSymbolAddress(&lastPtr, g_last);
    cudaMemsetAsync(lastPtr, 0xFF, (size_t)ncells * sizeof(int), 0);

    // 2) scatter
    int nt = (P + 3) / 4;
    bev_scatter_kernel<<<(nt + 255) / 256, 256>>>(coords, P);

    // 3) persistent pipelined gather (3 CTAs/SM x 148 SMs)
    static bool attr_set = false;
    if (!attr_set) {
        cudaFuncSetAttribute(bev_gather_kernel,
                             cudaFuncAttributeMaxDynamicSharedMemorySize,
                             2 * STAGE * 4);
        attr_set = true;
    }
    int gblocks = 148 * 3;
    if (gblocks > ntiles) gblocks = ntiles;
    bev_gather_kernel<<<gblocks, GT, 2 * STAGE * 4>>>(feats, out, ntiles);
}

// round 13
// speedup vs baseline: 1.2749x; 1.1398x over previous
#include <cuda_runtime.h>
#include <cuda_bf16.h>

#define BEV_H 512
#define BEV_W 512
#define BEV_C 64
#define HW (BEV_H * BEV_W)   // 262144 = 2^18

// Scratch: last-writer pillar index per BEV cell (up to 8 batches).
__device__ int g_last[8 * HW];
// Zero row for empty cells (zero-initialized, never written).
__device__ __align__(16) float g_zero[BEV_C];

// ---------------------------------------------------------------------------
// Scatter: last-occurrence-wins via atomicMax on pillar index.
// ---------------------------------------------------------------------------
__global__ void bev_scatter_kernel(const int* __restrict__ coords, int P) {
    int t = blockIdx.x * blockDim.x + threadIdx.x;
    int p0 = t * 4;
    if (p0 + 3 < P) {
        const int4* c4 = reinterpret_cast<const int4*>(coords + p0 * 3);
        int4 a  = __ldg(c4 + 0);  // b0 r0 c0 b1
        int4 bb = __ldg(c4 + 1);  // r1 c1 b2 r2
        int4 cc = __ldg(c4 + 2);  // c2 b3 r3 c3
        int bs[4] = {a.x, a.w, bb.z, cc.y};
        int rs[4] = {a.y, bb.x, bb.w, cc.z};
        int cs[4] = {a.z, bb.y, cc.x, cc.w};
#pragma unroll
        for (int k = 0; k < 4; k++) {
            int r = min(max(rs[k], 0), BEV_H - 1);
            int c = min(max(cs[k], 0), BEV_W - 1);
            atomicMax(&g_last[bs[k] * HW + r * BEV_W + c], p0 + k);
        }
    } else if (p0 < P) {
        for (int p = p0; p < P; p++) {
            int b = coords[3 * p + 0];
            int r = min(max(coords[3 * p + 1], 0), BEV_H - 1);
            int c = min(max(coords[3 * p + 2], 0), BEV_W - 1);
            atomicMax(&g_last[b * HW + r * BEV_W + c], p);
        }
    }
}

// ---------------------------------------------------------------------------
// Gather + transpose: warp-autonomous, ZERO smem / shuffle-free transpose.
// Warp owns 32 consecutive cells. Team (q=l&3, cw=l>>2) covers cells
// 4cw..4cw+3; in pass k (channel-quad), lane q loads chunk (q+4k) of each of
// its 4 cell rows -> lane holds 4 CONSECUTIVE cells x 4 channels. The store
// for channel e is a float4 along W gathered from components of the 4 loads
// (register MOVs only). Per STG.128 instruction: 4 q-groups x 8 lanes x 16B
// = 4 FULL 128B lines (2 wf/cell stores). Loads: per LDG.128 the warp covers
// 8 rows x 64B contiguous = 8 wf (4 wf/cell). Total 6 wf/cell.
// Passes are software-pipelined: pass k+1's loads issue before pass k's
// stores, keeping MLP high with only ~32 live data regs.
// ---------------------------------------------------------------------------
__device__ __forceinline__ const float4* row_ptr(const float* feats, int lc) {
    return reinterpret_cast<const float4*>(
        lc >= 0 ? feats + (size_t)lc * BEV_C : g_zero);
}

__global__ void __launch_bounds__(256) bev_gather_kernel(
    const float* __restrict__ feats,
    float* __restrict__ out) {
    const int t  = blockIdx.x * 256 + threadIdx.x;
    const int w  = t >> 5;          // global warp id
    const int l  = t & 31;
    const int q  = l & 3;           // chunk lane within team
    const int cw = l >> 2;          // team id: cells 4cw..4cw+3

    const int base = w * 32;        // first cell (32-aligned, in-batch)
    const int b    = base >> 18;
    const int pos  = base & (HW - 1);

    // Coalesced g_last load; team's 4 cell indices via shuffle.
    const int myLast = __ldg(&g_last[base + l]);
    const float4* rp[4];
#pragma unroll
    for (int r = 0; r < 4; r++)
        rp[r] = row_ptr(feats, __shfl_sync(0xffffffffu, myLast, 4 * cw + r));

    // Lane's store base: cells pos+4cw.. of channel column 4q (+16k +e).
    float* outb = out + (size_t)b * (BEV_C * HW) + pos + 4 * cw
                + (size_t)(4 * q) * HW;

    // ---- pass 0 loads: chunk q of each of the 4 cell rows ----
    float4 A[4], B[4];
#pragma unroll
    for (int r = 0; r < 4; r++) A[r] = __ldg(rp[r] + q);

#pragma unroll
    for (int k = 0; k < 4; k++) {
        // prefetch pass k+1 (issues before pass k's stores consume A)
        if (k < 3) {
#pragma unroll
            for (int r = 0; r < 4; r++) B[r] = __ldg(rp[r] + q + 4 * (k + 1));
        }

        // store pass k: channels 4(q+4k)+e, e=0..3; float4 along W
        float* oc = outb + (size_t)(16 * k) * HW;
        float4 s;
        s.x = A[0].x; s.y = A[1].x; s.z = A[2].x; s.w = A[3].x;
        *reinterpret_cast<float4*>(oc + 0 * (size_t)HW) = s;
        s.x = A[0].y; s.y = A[1].y; s.z = A[2].y; s.w = A[3].y;
        *reinterpret_cast<float4*>(oc + 1 * (size_t)HW) = s;
        s.x = A[0].z; s.y = A[1].z; s.z = A[2].z; s.w = A[3].z;
        *reinterpret_cast<float4*>(oc + 2 * (size_t)HW) = s;
        s.x = A[0].w; s.y = A[1].w; s.z = A[2].w; s.w = A[3].w;
        *reinterpret_cast<float4*>(oc + 3 * (size_t)HW) = s;

#pragma unroll
        for (int r = 0; r < 4; r++) A[r] = B[r];
    }
}

extern "C" void kernel_launch(void* const* d_in, const int* in_sizes, int n_in,
                              void* d_out, int out_size) {
    const float* feats  = (const float*)d_in[0];   // (P, 64) float32
    const int*   coords = (const int*)d_in[1];     // (P, 3) int32
    float*       out    = (float*)d_out;           // (B, 64, 512, 512) float32

    int P = in_sizes[0] / BEV_C;
    int B = out_size / (BEV_C * HW);
    if (B > 8) B = 8;
    int ncells = B * HW;

    // 1) init last-index grid to -1 (memset node; 0xFF bytes == -1 int)
    void* lastPtr = nullptr;
    cudaGetSymbolAddress(&lastPtr, g_last);
    cudaMemsetAsync(lastPtr, 0xFF, (size_t)ncells * sizeof(int), 0);

    // 2) scatter
    int nt = (P + 3) / 4;
    bev_scatter_kernel<<<(nt + 255) / 256, 256>>>(coords, P);

    // 3) gather + transpose: 32 cells per warp, 8 warps per CTA
    bev_gather_kernel<<<ncells / 256, 256>>>(feats, out);
}

// round 15
// speedup vs baseline: 1.2959x; 1.0165x over previous
#include <cuda_runtime.h>
#include <cuda_bf16.h>

#define BEV_H 512
#define BEV_W 512
#define BEV_C 64
#define HW (BEV_H * BEV_W)   // 262144 = 2^18

// Scratch: last-writer pillar index per BEV cell (up to 8 batches).
__device__ int g_last[8 * HW];
// Zero row for empty cells (zero-initialized, never written).
__device__ __align__(16) float g_zero[BEV_C];

// ---------------------------------------------------------------------------
// Scatter: last-occurrence-wins via atomicMax on pillar index.
// ---------------------------------------------------------------------------
__global__ void bev_scatter_kernel(const int* __restrict__ coords, int P) {
    int t = blockIdx.x * blockDim.x + threadIdx.x;
    int p0 = t * 4;
    if (p0 + 3 < P) {
        const int4* c4 = reinterpret_cast<const int4*>(coords + p0 * 3);
        int4 a  = __ldg(c4 + 0);  // b0 r0 c0 b1
        int4 bb = __ldg(c4 + 1);  // r1 c1 b2 r2
        int4 cc = __ldg(c4 + 2);  // c2 b3 r3 c3
        int bs[4] = {a.x, a.w, bb.z, cc.y};
        int rs[4] = {a.y, bb.x, bb.w, cc.z};
        int cs[4] = {a.z, bb.y, cc.x, cc.w};
#pragma unroll
        for (int k = 0; k < 4; k++) {
            int r = min(max(rs[k], 0), BEV_H - 1);
            int c = min(max(cs[k], 0), BEV_W - 1);
            atomicMax(&g_last[bs[k] * HW + r * BEV_W + c], p0 + k);
        }
    } else if (p0 < P) {
        for (int p = p0; p < P; p++) {
            int b = coords[3 * p + 0];
            int r = min(max(coords[3 * p + 1], 0), BEV_H - 1);
            int c = min(max(coords[3 * p + 2], 0), BEV_W - 1);
            atomicMax(&g_last[b * HW + r * BEV_W + c], p);
        }
    }
}

// ---------------------------------------------------------------------------
// Gather + transpose: warp-autonomous register transpose (R13 structure) with
// evict-first (__stcs) output stores so the 256MB write stream does not
// allocate/thrash L2 -> feats (51MB) stays L2-resident under default policy.
// Team (q=l&3, cw=l>>2) covers cells 4cw..4cw+3; pass k: lane q loads chunk
// (q+4k) of each of its 4 rows -> holds 4 consecutive cells x 4 channels;
// stores are float4 along W gathered from components (register MOVs only).
// 4 wf/cell loads + 2 wf/cell stores; passes software-pipelined.
// ---------------------------------------------------------------------------
__device__ __forceinline__ const float4* row_ptr(const float* feats, int lc) {
    return reinterpret_cast<const float4*>(
        lc >= 0 ? feats + (size_t)lc * BEV_C : g_zero);
}

__global__ void __launch_bounds__(256) bev_gather_kernel(
    const float* __restrict__ feats,
    float* __restrict__ out) {
    const int t  = blockIdx.x * 256 + threadIdx.x;
    const int w  = t >> 5;          // global warp id
    const int l  = t & 31;
    const int q  = l & 3;           // chunk lane within team
    const int cw = l >> 2;          // team id: cells 4cw..4cw+3

    const int base = w * 32;        // first cell (32-aligned, in-batch)
    const int b    = base >> 18;
    const int pos  = base & (HW - 1);

    // Coalesced g_last load; team's 4 cell indices via shuffle.
    const int myLast = __ldg(&g_last[base + l]);
    const float4* rp[4];
#pragma unroll
    for (int r = 0; r < 4; r++)
        rp[r] = row_ptr(feats, __shfl_sync(0xffffffffu, myLast, 4 * cw + r));

    // Lane's store base: cells pos+4cw.. of channel column 4q (+16k +e).
    float* outb = out + (size_t)b * (BEV_C * HW) + pos + 4 * cw
                + (size_t)(4 * q) * HW;

    // ---- pass 0 loads: chunk q of each of the 4 cell rows ----
    float4 A[4], B[4];
#pragma unroll
    for (int r = 0; r < 4; r++) A[r] = __ldg(rp[r] + q);

#pragma unroll
    for (int k = 0; k < 4; k++) {
        // prefetch pass k+1 (issues before pass k's stores consume A)
        if (k < 3) {
#pragma unroll
            for (int r = 0; r < 4; r++) B[r] = __ldg(rp[r] + q + 4 * (k + 1));
        }

        // store pass k: channels 4(q+4k)+e, e=0..3; float4 along W, evict-first
        float* oc = outb + (size_t)(16 * k) * HW;
        float4 s;
        s.x = A[0].x; s.y = A[1].x; s.z = A[2].x; s.w = A[3].x;
        __stcs(reinterpret_cast<float4*>(oc + 0 * (size_t)HW), s);
        s.x = A[0].y; s.y = A[1].y; s.z = A[2].y; s.w = A[3].y;
        __stcs(reinterpret_cast<float4*>(oc + 1 * (size_t)HW), s);
        s.x = A[0].z; s.y = A[1].z; s.z = A[2].z; s.w = A[3].z;
        __stcs(reinterpret_cast<float4*>(oc + 2 * (size_t)HW), s);
        s.x = A[0].w; s.y = A[1].w; s.z = A[2].w; s.w = A[3].w;
        __stcs(reinterpret_cast<float4*>(oc + 3 * (size_t)HW), s);

#pragma unroll
        for (int r = 0; r < 4; r++) A[r] = B[r];
    }
}

extern "C" void kernel_launch(void* const* d_in, const int* in_sizes, int n_in,
                              void* d_out, int out_size) {
    const float* feats  = (const float*)d_in[0];   // (P, 64) float32
    const int*   coords = (const int*)d_in[1];     // (P, 3) int32
    float*       out    = (float*)d_out;           // (B, 64, 512, 512) float32

    int P = in_sizes[0] / BEV_C;
    int B = out_size / (BEV_C * HW);
    if (B > 8) B = 8;
    int ncells = B * HW;

    // 1) init last-index grid to -1 (memset node; 0xFF bytes == -1 int)
    void* lastPtr = nullptr;
    cudaGetSymbolAddress(&lastPtr, g_last);
    cudaMemsetAsync(lastPtr, 0xFF, (size_t)ncells * sizeof(int), 0);

    // 2) scatter
    int nt = (P + 3) / 4;
    bev_scatter_kernel<<<(nt + 255) / 256, 256>>>(coords, P);

    // 3) gather + transpose: 32 cells per warp, 8 warps per CTA
    bev_gather_kernel<<<ncells / 256, 256>>>(feats, out);
}